// round 8
// baseline (speedup 1.0000x reference)
#include <cuda_runtime.h>
#include <cstdint>

#define NB 16
#define NP 8192
#define NC 32
#define NG 512
#define NM 32

// ---- scratch (static __device__, no allocations) ----
__device__ float g_xt[NB * 3 * NP];   // xyz transposed: [b][coord][point]
__device__ float g_np[NB * NP];       // point squared norms
__device__ int   g_fps[NB * NG];      // FPS indices
__device__ float g_cent[NB * NG * 3]; // center coords (pre-reorder)
__device__ float g_cnorm[NB * NG];    // center squared norms
__device__ int   g_order[NB * NG];    // morton order

// monotonic float->uint key; -0.0 treated as +0.0
__device__ __forceinline__ unsigned fkey(float f) {
    unsigned u = __float_as_uint(f);
    if (u == 0x80000000u) u = 0u;
    return u ^ ((unsigned)((int)u >> 31) | 0x80000000u);
}

// SLP-lane model: rn(rn(x*x + z*z) + y*y)   <-- the third (untested) chain tree
__device__ __forceinline__ float norm3(float x, float y, float z) {
    return __fadd_rn(__fadd_rn(__fmul_rn(x, x), __fmul_rn(z, z)), __fmul_rn(y, y));
}

// ---------------------------------------------------------------------------
// K0: transpose xyz to SoA + precompute point norms
// ---------------------------------------------------------------------------
__global__ void k_pre(const float* __restrict__ xyz) {
    int i = blockIdx.x * blockDim.x + threadIdx.x;
    if (i >= NB * NP) return;
    int b = i / NP, p = i - b * NP;
    float x = xyz[3 * i + 0], y = xyz[3 * i + 1], z = xyz[3 * i + 2];
    g_xt[(b * 3 + 0) * NP + p] = x;
    g_xt[(b * 3 + 1) * NP + p] = y;
    g_xt[(b * 3 + 2) * NP + p] = z;
    g_np[i] = norm3(x, y, z);
}

// ---------------------------------------------------------------------------
// K1: farthest point sampling. One block (1024 thr) per batch, points in regs.
// Elementwise fusion site: asc chain (R2, proven flip-free; argmax gaps huge).
// ---------------------------------------------------------------------------
__global__ void __launch_bounds__(1024, 1) k_fps() {
    int b = blockIdx.x, t = threadIdx.x;
    const float* X = &g_xt[(b * 3 + 0) * NP];
    const float* Y = &g_xt[(b * 3 + 1) * NP];
    const float* Z = &g_xt[(b * 3 + 2) * NP];

    float px[8], py[8], pz[8], mind[8];
#pragma unroll
    for (int r = 0; r < 8; r++) {
        int i = t + r * 1024;
        px[r] = X[i]; py[r] = Y[i]; pz[r] = Z[i];
        mind[r] = 1e10f;
    }

    __shared__ float s_last[3];
    __shared__ unsigned s_pk[32], s_pi[32];
    __shared__ unsigned s_widx;
    if (t == 0) {
        s_last[0] = X[0]; s_last[1] = Y[0]; s_last[2] = Z[0];
        g_fps[b * NG] = 0;
    }
    __syncthreads();

    int lane = t & 31, w = t >> 5;
    for (int k = 1; k < NG; k++) {
        float lx = s_last[0], ly = s_last[1], lz = s_last[2];
        float bv = -1.0f; unsigned bi = 0xFFFFFFFFu;
#pragma unroll
        for (int r = 0; r < 8; r++) {
            float dx = __fsub_rn(px[r], lx);
            float dy = __fsub_rn(py[r], ly);
            float dz = __fsub_rn(pz[r], lz);
            float d = __fadd_rn(__fadd_rn(__fmul_rn(dx, dx), __fmul_rn(dy, dy)),
                                __fmul_rn(dz, dz));
            float m = fminf(mind[r], d);
            mind[r] = m;
            if (m > bv) { bv = m; bi = (unsigned)(t + r * 1024); } // ascending idx -> first-max kept
        }
        // argmax: values are >= 0 so raw bits are monotonic
        unsigned key  = __float_as_uint(bv);
        unsigned wmax = __reduce_max_sync(0xFFFFFFFFu, key);
        unsigned cand = (key == wmax) ? bi : 0xFFFFFFFFu;
        unsigned wi   = __reduce_min_sync(0xFFFFFFFFu, cand);
        if (lane == 0) { s_pk[w] = wmax; s_pi[w] = wi; }
        __syncthreads();
        if (w == 0) {
            unsigned kk = s_pk[lane], ii = s_pi[lane];
            unsigned gmax = __reduce_max_sync(0xFFFFFFFFu, kk);
            unsigned c2   = (kk == gmax) ? ii : 0xFFFFFFFFu;
            unsigned gi   = __reduce_min_sync(0xFFFFFFFFu, c2);
            if (lane == 0) { s_widx = gi; g_fps[b * NG + k] = (int)gi; }
        }
        __syncthreads();
        unsigned widx = s_widx;
        if ((widx & 1023u) == (unsigned)t) {   // winner owner publishes coords (regs only)
            int rw = widx >> 10;
            float wx = px[0], wy = py[0], wz = pz[0];
#pragma unroll
            for (int r = 1; r < 8; r++)
                if (rw == r) { wx = px[r]; wy = py[r]; wz = pz[r]; }
            s_last[0] = wx; s_last[1] = wy; s_last[2] = wz;
        }
        __syncthreads();
    }
}

// ---------------------------------------------------------------------------
// K2: greedy NN chain over centers ("morton"). asc-fma dot; gaps flip-immune.
// ---------------------------------------------------------------------------
__global__ void __launch_bounds__(512, 1) k_morton() {
    int b = blockIdx.x, j = threadIdx.x;
    int fi = g_fps[b * NG + j];
    const float* X = &g_xt[(b * 3 + 0) * NP];
    const float* Y = &g_xt[(b * 3 + 1) * NP];
    const float* Z = &g_xt[(b * 3 + 2) * NP];
    float cx = X[fi], cy = Y[fi], cz = Z[fi];
    float nj = norm3(cx, cy, cz);
    g_cent[(b * NG + j) * 3 + 0] = cx;
    g_cent[(b * NG + j) * 3 + 1] = cy;
    g_cent[(b * NG + j) * 3 + 2] = cz;
    g_cnorm[b * NG + j] = nj;

    bool alive = (j != 0); // column 0 is inf from the start
    __shared__ float s_cur[4];
    __shared__ unsigned s_pk[16], s_pi[16], s_w;
    if (j == 0) {
        s_cur[0] = cx; s_cur[1] = cy; s_cur[2] = cz; s_cur[3] = nj;
        g_order[b * NG] = 0;
    }
    __syncthreads();

    int lane = j & 31, w = j >> 5;
    for (int k = 1; k < NG; k++) {
        float qx = s_cur[0], qy = s_cur[1], qz = s_cur[2], qn = s_cur[3];
        float dot = fmaf(qz, cz, fmaf(qy, cy, __fmul_rn(qx, cx)));
        float d2 = __fsub_rn(__fadd_rn(qn, nj), __fmul_rn(2.0f, dot));
        float dv = __fsqrt_rn(fmaxf(d2, 0.0f)); // compare in sqrt-space like the reference
        unsigned key  = alive ? __float_as_uint(dv) : 0xFFFFFFFFu; // dv>=0 -> bits monotonic
        unsigned kmin = __reduce_min_sync(0xFFFFFFFFu, key);
        unsigned cand = (key == kmin) ? (unsigned)j : 0xFFFFFFFFu;
        unsigned imin = __reduce_min_sync(0xFFFFFFFFu, cand);
        if (lane == 0) { s_pk[w] = kmin; s_pi[w] = imin; }
        __syncthreads();
        if (w == 0 && lane < 16) {
            unsigned kk = s_pk[lane], ii = s_pi[lane];
            unsigned gmin = __reduce_min_sync(0xFFFFu, kk);
            unsigned c2   = (kk == gmin) ? ii : 0xFFFFFFFFu;
            unsigned gi   = __reduce_min_sync(0xFFFFu, c2);
            if (lane == 0) { s_w = gi; g_order[b * NG + k] = (int)gi; }
        }
        __syncthreads();
        if ((unsigned)j == s_w) {
            alive = false;
            s_cur[0] = cx; s_cur[1] = cy; s_cur[2] = cz; s_cur[3] = nj;
        }
        __syncthreads();
    }
}

// ---------------------------------------------------------------------------
// K3: KNN top-32 + assembly. asc-fma dot; PN = (x2+z2)+y2 tree (this round's
// single variable). Low-index ties (confirmed).
// ---------------------------------------------------------------------------
__global__ void __launch_bounds__(256, 4) k_knn(const float* __restrict__ x,
                                                float* __restrict__ out) {
    __shared__ float sd[NP];          // 32KB of d2
    __shared__ float s_xq[NC];
    __shared__ int s_knn[NM];
    __shared__ unsigned s_pk[8], s_pi[8], s_w;

    int bg = blockIdx.x;
    int b = bg >> 9;
    int t = threadIdx.x;
    int gorig = g_order[bg];
    int cbase = b * NG + gorig;
    float cx = g_cent[cbase * 3 + 0];
    float cy = g_cent[cbase * 3 + 1];
    float cz = g_cent[cbase * 3 + 2];
    float nc = g_cnorm[cbase];
    int qi = g_fps[cbase];
    if (t < NC) s_xq[t] = x[((size_t)b * NP + qi) * NC + t];

    const float* X = &g_xt[(b * 3 + 0) * NP];
    const float* Y = &g_xt[(b * 3 + 1) * NP];
    const float* Z = &g_xt[(b * 3 + 2) * NP];
    const float* PN = &g_np[b * NP];
    const float INF = __int_as_float(0x7f800000);

    float bv = INF; unsigned bi = 0xFFFFFFFFu;
#pragma unroll
    for (int r = 0; r < 32; r++) {
        int i = t + r * 256;
        float dot = fmaf(cz, Z[i], fmaf(cy, Y[i], __fmul_rn(cx, X[i]))); // asc-fma (gemm)
        float d2 = __fsub_rn(__fadd_rn(nc, PN[i]), __fmul_rn(2.0f, dot));
        sd[i] = d2;
        if (d2 < bv) { bv = d2; bi = (unsigned)i; }
    }
    __syncthreads();

    int lane = t & 31, w = t >> 5;
    for (int k = 0; k < NM; k++) {
        unsigned key  = fkey(bv);
        unsigned kmin = __reduce_min_sync(0xFFFFFFFFu, key);
        unsigned cand = (key == kmin) ? bi : 0xFFFFFFFFu;
        unsigned imin = __reduce_min_sync(0xFFFFFFFFu, cand);
        if (lane == 0) { s_pk[w] = kmin; s_pi[w] = imin; }
        __syncthreads();
        if (w == 0 && lane < 8) {
            unsigned kk = s_pk[lane], ii = s_pi[lane];
            unsigned gmin = __reduce_min_sync(0xFFu, kk);
            unsigned c2   = (kk == gmin) ? ii : 0xFFFFFFFFu;
            unsigned gi   = __reduce_min_sync(0xFFu, c2);
            if (lane == 0) { s_w = gi; s_knn[k] = (int)gi; }
        }
        __syncthreads();
        unsigned wi = s_w;
        if ((wi & 255u) == (unsigned)t) {  // only winner's owner rescans its 32
            sd[wi] = INF;
            bv = INF; bi = 0xFFFFFFFFu;
#pragma unroll
            for (int r = 0; r < 32; r++) {
                int i = t + r * 256;
                float d = sd[i];
                if (d < bv) { bv = d; bi = (unsigned)i; }
            }
        }
    }
    __syncthreads();

    // output: nbh[bg][m][0:32] = x[nbr]-xq ; nbh[bg][m][32:64] = xq
    const float* xb = x + (size_t)b * NP * NC;
    size_t base = (size_t)bg * (NM * 2 * NC);
    for (int v = t; v < NM * 2 * NC; v += 256) {
        int m = v >> 6, c = v & 63;
        float val;
        if (c < NC) val = __fsub_rn(xb[(size_t)s_knn[m] * NC + c], s_xq[c]);
        else        val = s_xq[c - NC];
        out[base + v] = val;
    }
    if (t < 3)
        out[(size_t)NB * NG * NM * 2 * NC + (size_t)bg * 3 + t] = g_cent[cbase * 3 + t];
}

// ---------------------------------------------------------------------------
extern "C" void kernel_launch(void* const* d_in, const int* in_sizes, int n_in,
                              void* d_out, int out_size) {
    const float* x   = (const float*)d_in[0];
    const float* xyz = (const float*)d_in[1];
    if (n_in >= 2 && in_sizes[0] == NB * NP * 3) { // defensive: metadata order swap
        const float* tmp = x; x = xyz; xyz = tmp;
    }
    float* out = (float*)d_out;
    k_pre<<<(NB * NP + 255) / 256, 256>>>(xyz);
    k_fps<<<NB, 1024>>>();
    k_morton<<<NB, 512>>>();
    k_knn<<<NB * NG, 256>>>(x, out);
}

// round 9
// speedup vs baseline: 1.2439x; 1.2439x over previous
#include <cuda_runtime.h>
#include <cstdint>

#define NB 16
#define NP 8192
#define NC 32
#define NG 512
#define NM 32

// ---- scratch (static __device__, no allocations) ----
__device__ float g_xt[NB * 3 * NP];   // xyz transposed: [b][coord][point]
__device__ float g_np[NB * NP];       // point squared norms
__device__ int   g_fps[NB * NG];      // FPS indices
__device__ float g_cent[NB * NG * 3]; // center coords (fps order)
__device__ float g_cnorm[NB * NG];    // center squared norms
__device__ int   g_order[NB * NG];    // morton order
__device__ float4 g_tmp[(size_t)NB * NG * 512]; // nbh rows in FPS order (64MB)

typedef unsigned long long ull;

// packed f32x2 helpers (per-lane IEEE rn -> bit-exact)
__device__ __forceinline__ ull pk2(float lo, float hi) {
    ull r;
    asm("mov.b64 %0, {%1, %2};" : "=l"(r) : "r"(__float_as_uint(lo)), "r"(__float_as_uint(hi)));
    return r;
}
__device__ __forceinline__ float2 upk2(ull v) {
    unsigned lo, hi;
    asm("mov.b64 {%0, %1}, %2;" : "=r"(lo), "=r"(hi) : "l"(v));
    return make_float2(__uint_as_float(lo), __uint_as_float(hi));
}
__device__ __forceinline__ ull padd(ull a, ull b) {
    ull r; asm("add.rn.f32x2 %0, %1, %2;" : "=l"(r) : "l"(a), "l"(b)); return r;
}
__device__ __forceinline__ ull pmul(ull a, ull b) {
    ull r; asm("mul.rn.f32x2 %0, %1, %2;" : "=l"(r) : "l"(a), "l"(b)); return r;
}

// monotonic float->uint key; -0.0 treated as +0.0
__device__ __forceinline__ unsigned fkey(float f) {
    unsigned u = __float_as_uint(f);
    if (u == 0x80000000u) u = 0u;
    return u ^ ((unsigned)((int)u >> 31) | 0x80000000u);
}

// PN tree (proven): rn(rn(x*x + z*z) + y*y)
__device__ __forceinline__ float norm3(float x, float y, float z) {
    return __fadd_rn(__fadd_rn(__fmul_rn(x, x), __fmul_rn(z, z)), __fmul_rn(y, y));
}

// ---------------------------------------------------------------------------
// K0: transpose xyz to SoA + precompute point norms
// ---------------------------------------------------------------------------
__global__ void k_pre(const float* __restrict__ xyz) {
    int i = blockIdx.x * blockDim.x + threadIdx.x;
    if (i >= NB * NP) return;
    int b = i / NP, p = i - b * NP;
    float x = xyz[3 * i + 0], y = xyz[3 * i + 1], z = xyz[3 * i + 2];
    g_xt[(b * 3 + 0) * NP + p] = x;
    g_xt[(b * 3 + 1) * NP + p] = y;
    g_xt[(b * 3 + 2) * NP + p] = z;
    g_np[i] = norm3(x, y, z);
}

// ---------------------------------------------------------------------------
// K1: FPS. One 1024-thread block per batch; thread t owns points [8t, 8t+8).
// Distance chain rn(rn(rn(dx^2)+rn(dy^2))+rn(dz^2)) via packed f32x2 (bit-exact:
// dx = rn(px + (-lx)) == rn(px - lx)). Tail: materialize centers + cnorms.
// ---------------------------------------------------------------------------
__global__ void __launch_bounds__(1024, 1) k_fps() {
    int b = blockIdx.x, t = threadIdx.x;
    const float* X = &g_xt[(b * 3 + 0) * NP];
    const float* Y = &g_xt[(b * 3 + 1) * NP];
    const float* Z = &g_xt[(b * 3 + 2) * NP];
    const ull* X2 = (const ull*)X;
    const ull* Y2 = (const ull*)Y;
    const ull* Z2 = (const ull*)Z;

    ull pxp[4], pyp[4], pzp[4];
    float mind[8];
#pragma unroll
    for (int r = 0; r < 4; r++) {
        pxp[r] = X2[t * 4 + r];
        pyp[r] = Y2[t * 4 + r];
        pzp[r] = Z2[t * 4 + r];
    }
#pragma unroll
    for (int r = 0; r < 8; r++) mind[r] = 1e10f;

    __shared__ float s_last[3];
    __shared__ unsigned s_pk[32], s_pi[32];
    __shared__ unsigned s_widx;
    if (t == 0) {
        s_last[0] = X[0]; s_last[1] = Y[0]; s_last[2] = Z[0];
        g_fps[b * NG] = 0;
    }
    __syncthreads();

    int lane = t & 31, w = t >> 5;
    unsigned base = (unsigned)t * 8u;
    for (int k = 1; k < NG; k++) {
        float lx = s_last[0], ly = s_last[1], lz = s_last[2];
        ull nlx = pk2(-lx, -lx), nly = pk2(-ly, -ly), nlz = pk2(-lz, -lz);
        float bv = -1.0f; unsigned bi = 0xFFFFFFFFu;
#pragma unroll
        for (int r = 0; r < 4; r++) {
            ull dx = padd(pxp[r], nlx);
            ull dy = padd(pyp[r], nly);
            ull dz = padd(pzp[r], nlz);
            ull dd = padd(padd(pmul(dx, dx), pmul(dy, dy)), pmul(dz, dz));
            float2 d = upk2(dd);
            float m0 = fminf(mind[2 * r], d.x);
            mind[2 * r] = m0;
            if (m0 > bv) { bv = m0; bi = base + 2 * r; }
            float m1 = fminf(mind[2 * r + 1], d.y);
            mind[2 * r + 1] = m1;
            if (m1 > bv) { bv = m1; bi = base + 2 * r + 1; }
        }
        // argmax: values >= 0 so raw bits monotonic; low-index ties
        unsigned key  = __float_as_uint(bv);
        unsigned wmax = __reduce_max_sync(0xFFFFFFFFu, key);
        unsigned cand = (key == wmax) ? bi : 0xFFFFFFFFu;
        unsigned wi   = __reduce_min_sync(0xFFFFFFFFu, cand);
        if (lane == 0) { s_pk[w] = wmax; s_pi[w] = wi; }
        __syncthreads();
        if (w == 0) {
            unsigned kk = s_pk[lane], ii = s_pi[lane];
            unsigned gmax = __reduce_max_sync(0xFFFFFFFFu, kk);
            unsigned c2   = (kk == gmax) ? ii : 0xFFFFFFFFu;
            unsigned gi   = __reduce_min_sync(0xFFFFFFFFu, c2);
            if (lane == 0) { s_widx = gi; g_fps[b * NG + k] = (int)gi; }
        }
        __syncthreads();
        unsigned widx = s_widx;
        if ((widx >> 3) == (unsigned)t) {  // winner owner publishes coords
            int r = (int)(widx & 7u);
            int h = r >> 1;
            ull sx = pxp[0], sy = pyp[0], sz = pzp[0];
#pragma unroll
            for (int q = 1; q < 4; q++)
                if (h == q) { sx = pxp[q]; sy = pyp[q]; sz = pzp[q]; }
            float2 fx = upk2(sx), fy = upk2(sy), fz = upk2(sz);
            bool hi = (r & 1);
            s_last[0] = hi ? fx.y : fx.x;
            s_last[1] = hi ? fy.y : fy.x;
            s_last[2] = hi ? fz.y : fz.x;
        }
        __syncthreads();
    }

    // tail: centers + cnorms in FPS order (knn blocks consume these)
    if (t < NG) {
        int fi = g_fps[b * NG + t];
        float cx = X[fi], cy = Y[fi], cz = Z[fi];
        g_cent[(b * NG + t) * 3 + 0] = cx;
        g_cent[(b * NG + t) * 3 + 1] = cy;
        g_cent[(b * NG + t) * 3 + 2] = cz;
        g_cnorm[b * NG + t] = norm3(cx, cy, cz);
    }
}

// ---------------------------------------------------------------------------
// K2: combined kernel. Blocks [0,16): morton chain (256 thr, 2 centers/thread).
// Blocks [16, 16+8192): KNN top-32 in FPS order -> g_tmp.
// ---------------------------------------------------------------------------
__global__ void __launch_bounds__(256, 4) k_mk(const float* __restrict__ x) {
    __shared__ float sd[NP];          // knn: d2; morton: center arrays
    __shared__ float s_xq[NC];
    __shared__ int s_knn[NM];
    __shared__ unsigned s_pk[8], s_pi[8], s_w;

    int t = threadIdx.x;
    int lane = t & 31, w = t >> 5;

    if (blockIdx.x < NB) {
        // ---------------- morton ----------------
        int b = blockIdx.x;
        float* s_cx = sd;
        float* s_cy = sd + NG;
        float* s_cz = sd + 2 * NG;
        float* s_cn = sd + 3 * NG;
        for (int j = t; j < NG; j += 256) {
            s_cx[j] = g_cent[(b * NG + j) * 3 + 0];
            s_cy[j] = g_cent[(b * NG + j) * 3 + 1];
            s_cz[j] = g_cent[(b * NG + j) * 3 + 2];
            s_cn[j] = g_cnorm[b * NG + j];
        }
        if (t == 0) { s_w = 0; g_order[b * NG] = 0; }
        __syncthreads();

        int j1 = t, j2 = t + 256;
        float c1x = s_cx[j1], c1y = s_cy[j1], c1z = s_cz[j1], n1 = s_cn[j1];
        float c2x = s_cx[j2], c2y = s_cy[j2], c2z = s_cz[j2], n2 = s_cn[j2];
        bool a1 = (j1 != 0), a2 = true;

        for (int k = 1; k < NG; k++) {
            int wi0 = (int)s_w;
            float qx = s_cx[wi0], qy = s_cy[wi0], qz = s_cz[wi0], qn = s_cn[wi0];
            // center 1 (same fma chain + combine + sqrt as R8)
            float dot1 = fmaf(qz, c1z, fmaf(qy, c1y, __fmul_rn(qx, c1x)));
            float d21 = __fsub_rn(__fadd_rn(qn, n1), __fmul_rn(2.0f, dot1));
            float dv1 = __fsqrt_rn(fmaxf(d21, 0.0f));
            unsigned k1 = a1 ? __float_as_uint(dv1) : 0xFFFFFFFFu;
            // center 2
            float dot2 = fmaf(qz, c2z, fmaf(qy, c2y, __fmul_rn(qx, c2x)));
            float d22 = __fsub_rn(__fadd_rn(qn, n2), __fmul_rn(2.0f, dot2));
            float dv2 = __fsqrt_rn(fmaxf(d22, 0.0f));
            unsigned k2 = a2 ? __float_as_uint(dv2) : 0xFFFFFFFFu;
            // thread-local pre-min; tie -> j1 (lower index)
            unsigned kk = (k1 <= k2) ? k1 : k2;
            unsigned ii = (k1 <= k2) ? (unsigned)j1 : (unsigned)j2;

            unsigned kmin = __reduce_min_sync(0xFFFFFFFFu, kk);
            unsigned cand = (kk == kmin) ? ii : 0xFFFFFFFFu;
            unsigned imin = __reduce_min_sync(0xFFFFFFFFu, cand);
            if (lane == 0) { s_pk[w] = kmin; s_pi[w] = imin; }
            __syncthreads();
            if (w == 0 && lane < 8) {
                unsigned kb = s_pk[lane], ib = s_pi[lane];
                unsigned gmin = __reduce_min_sync(0xFFu, kb);
                unsigned cb   = (kb == gmin) ? ib : 0xFFFFFFFFu;
                unsigned gi   = __reduce_min_sync(0xFFu, cb);
                if (lane == 0) { s_w = gi; g_order[b * NG + k] = (int)gi; }
            }
            __syncthreads();
            int wn = (int)s_w;
            if (j1 == wn) a1 = false;
            if (j2 == wn) a2 = false;
        }
        return;
    }

    // ---------------- knn (FPS order, writes g_tmp) ----------------
    int bg = blockIdx.x - NB;
    int b = bg >> 9;
    float cx = g_cent[bg * 3 + 0];
    float cy = g_cent[bg * 3 + 1];
    float cz = g_cent[bg * 3 + 2];
    float nc = g_cnorm[bg];
    int qi = g_fps[bg];
    if (t < NC) s_xq[t] = x[((size_t)b * NP + qi) * NC + t];

    const float* X = &g_xt[(b * 3 + 0) * NP];
    const float* Y = &g_xt[(b * 3 + 1) * NP];
    const float* Z = &g_xt[(b * 3 + 2) * NP];
    const float* PN = &g_np[b * NP];
    const float INF = __int_as_float(0x7f800000);

    float bv = INF; unsigned bi = 0xFFFFFFFFu;
#pragma unroll
    for (int r = 0; r < 32; r++) {
        int i = t + r * 256;
        float dot = fmaf(cz, Z[i], fmaf(cy, Y[i], __fmul_rn(cx, X[i]))); // asc-fma
        float d2 = __fsub_rn(__fadd_rn(nc, PN[i]), __fmul_rn(2.0f, dot));
        sd[i] = d2;
        if (d2 < bv) { bv = d2; bi = (unsigned)i; }
    }
    __syncthreads();

    for (int k = 0; k < NM; k++) {
        unsigned key  = fkey(bv);
        unsigned kmin = __reduce_min_sync(0xFFFFFFFFu, key);
        unsigned cand = (key == kmin) ? bi : 0xFFFFFFFFu;
        unsigned imin = __reduce_min_sync(0xFFFFFFFFu, cand);
        if (lane == 0) { s_pk[w] = kmin; s_pi[w] = imin; }
        __syncthreads();
        if (w == 0 && lane < 8) {
            unsigned kk = s_pk[lane], ii = s_pi[lane];
            unsigned gmin = __reduce_min_sync(0xFFu, kk);
            unsigned c2   = (kk == gmin) ? ii : 0xFFFFFFFFu;
            unsigned gi   = __reduce_min_sync(0xFFu, c2);
            if (lane == 0) { s_w = gi; s_knn[k] = (int)gi; }
        }
        __syncthreads();
        unsigned wi = s_w;
        if ((wi & 255u) == (unsigned)t) {
            sd[wi] = INF;
            bv = INF; bi = 0xFFFFFFFFu;
#pragma unroll
            for (int r = 0; r < 32; r++) {
                int i = t + r * 256;
                float d = sd[i];
                if (d < bv) { bv = d; bi = (unsigned)i; }
            }
        }
    }
    __syncthreads();

    // write nbh row (FPS order) to g_tmp
    const float* xb = x + (size_t)b * NP * NC;
    float* trow = (float*)&g_tmp[(size_t)bg * 512];
    for (int v = t; v < NM * 2 * NC; v += 256) {
        int m = v >> 6, c = v & 63;
        float val;
        if (c < NC) val = __fsub_rn(xb[(size_t)s_knn[m] * NC + c], s_xq[c]);
        else        val = s_xq[c - NC];
        trow[v] = val;
    }
}

// ---------------------------------------------------------------------------
// K3: scatter rows by morton order + write centers
// ---------------------------------------------------------------------------
__global__ void __launch_bounds__(256, 8) k_scat(float* __restrict__ out) {
    int bg = blockIdx.x;
    int b = bg >> 9;
    int t = threadIdx.x;
    int g = g_order[bg];
    const float4* src = &g_tmp[((size_t)b * NG + g) * 512];
    float4* dst = (float4*)out + (size_t)bg * 512;
    dst[t] = src[t];
    dst[t + 256] = src[t + 256];
    if (t < 3)
        out[(size_t)NB * NG * NM * 2 * NC + (size_t)bg * 3 + t] =
            g_cent[(b * NG + g) * 3 + t];
}

// ---------------------------------------------------------------------------
extern "C" void kernel_launch(void* const* d_in, const int* in_sizes, int n_in,
                              void* d_out, int out_size) {
    const float* x   = (const float*)d_in[0];
    const float* xyz = (const float*)d_in[1];
    if (n_in >= 2 && in_sizes[0] == NB * NP * 3) { // defensive: metadata order swap
        const float* tmp = x; x = xyz; xyz = tmp;
    }
    float* out = (float*)d_out;
    k_pre<<<(NB * NP + 255) / 256, 256>>>(xyz);
    k_fps<<<NB, 1024>>>();
    k_mk<<<NB + NB * NG, 256>>>(x);
    k_scat<<<NB * NG, 256>>>(out);
}

// round 12
// speedup vs baseline: 1.5318x; 1.2314x over previous
#include <cuda_runtime.h>
#include <cstdint>

#define NB 16
#define NP 8192
#define NC 32
#define NG 512
#define NM 32
#define CAP2 224

// ---- scratch (static __device__, no allocations) ----
__device__ float g_xt[NB * 3 * NP];   // xyz transposed: [b][coord][point]
__device__ int   g_fps[NB * NG];      // FPS indices
__device__ float g_cent[NB * NG * 3]; // center coords (fps order)
__device__ float g_cnorm[NB * NG];    // center squared norms
__device__ int   g_order[NB * NG];    // morton order
__device__ float4 g_tmp[(size_t)NB * NG * 512]; // nbh rows in FPS order (64MB)

typedef unsigned long long ull;

// packed f32x2 helpers (per-lane IEEE rn -> bit-exact)
__device__ __forceinline__ ull pk2(float lo, float hi) {
    ull r;
    asm("mov.b64 %0, {%1, %2};" : "=l"(r) : "r"(__float_as_uint(lo)), "r"(__float_as_uint(hi)));
    return r;
}
__device__ __forceinline__ float2 upk2(ull v) {
    unsigned lo, hi;
    asm("mov.b64 {%0, %1}, %2;" : "=r"(lo), "=r"(hi) : "l"(v));
    return make_float2(__uint_as_float(lo), __uint_as_float(hi));
}
__device__ __forceinline__ ull padd(ull a, ull b) {
    ull r; asm("add.rn.f32x2 %0, %1, %2;" : "=l"(r) : "l"(a), "l"(b)); return r;
}
__device__ __forceinline__ ull pmul(ull a, ull b) {
    ull r; asm("mul.rn.f32x2 %0, %1, %2;" : "=l"(r) : "l"(a), "l"(b)); return r;
}

// monotonic float->uint key; -0.0 treated as +0.0
__device__ __forceinline__ unsigned fkey(float f) {
    unsigned u = __float_as_uint(f);
    if (u == 0x80000000u) u = 0u;
    return u ^ ((unsigned)((int)u >> 31) | 0x80000000u);
}

// PN tree (proven): rn(rn(x*x + z*z) + y*y)
__device__ __forceinline__ float norm3(float x, float y, float z) {
    return __fadd_rn(__fadd_rn(__fmul_rn(x, x), __fmul_rn(z, z)), __fmul_rn(y, y));
}

// ---------------------------------------------------------------------------
// K0: transpose xyz to SoA
// ---------------------------------------------------------------------------
__global__ void k_pre(const float* __restrict__ xyz) {
    int i = blockIdx.x * blockDim.x + threadIdx.x;
    if (i >= NB * NP) return;
    int b = i / NP, p = i - b * NP;
    g_xt[(b * 3 + 0) * NP + p] = xyz[3 * i + 0];
    g_xt[(b * 3 + 1) * NP + p] = xyz[3 * i + 1];
    g_xt[(b * 3 + 2) * NP + p] = xyz[3 * i + 2];
}

// ---------------------------------------------------------------------------
// K1: FPS. 1024 thr/block, points in regs (packed f32x2) + smem mirror so
// warp0 publishes the winner coords directly (2 barriers/iter, not 3).
// Dynamic smem: 3 * 4096 ull = 96KB.
// ---------------------------------------------------------------------------
__global__ void __launch_bounds__(1024, 1) k_fps() {
    extern __shared__ ull dsm[];
    ull* sx = dsm;
    ull* sy = dsm + 4096;
    ull* sz = dsm + 8192;

    int b = blockIdx.x, t = threadIdx.x;
    const float* X = &g_xt[(b * 3 + 0) * NP];
    const float* Y = &g_xt[(b * 3 + 1) * NP];
    const float* Z = &g_xt[(b * 3 + 2) * NP];
    const ull* X2 = (const ull*)X;
    const ull* Y2 = (const ull*)Y;
    const ull* Z2 = (const ull*)Z;

    ull pxp[4], pyp[4], pzp[4];
    float mind[8];
#pragma unroll
    for (int r = 0; r < 4; r++) {
        pxp[r] = X2[t * 4 + r];
        pyp[r] = Y2[t * 4 + r];
        pzp[r] = Z2[t * 4 + r];
        sx[t * 4 + r] = pxp[r];
        sy[t * 4 + r] = pyp[r];
        sz[t * 4 + r] = pzp[r];
    }
#pragma unroll
    for (int r = 0; r < 8; r++) mind[r] = 1e10f;

    __shared__ float s_last[3];
    __shared__ unsigned s_pk[32], s_pi[32];
    if (t == 0) {
        s_last[0] = X[0]; s_last[1] = Y[0]; s_last[2] = Z[0];
        g_fps[b * NG] = 0;
    }
    __syncthreads();

    int lane = t & 31, w = t >> 5;
    unsigned base = (unsigned)t * 8u;
    for (int k = 1; k < NG; k++) {
        float lx = s_last[0], ly = s_last[1], lz = s_last[2];
        ull nlx = pk2(-lx, -lx), nly = pk2(-ly, -ly), nlz = pk2(-lz, -lz);
        float bv = -1.0f; unsigned bi = 0xFFFFFFFFu;
#pragma unroll
        for (int r = 0; r < 4; r++) {
            ull dx = padd(pxp[r], nlx);
            ull dy = padd(pyp[r], nly);
            ull dz = padd(pzp[r], nlz);
            ull dd = padd(padd(pmul(dx, dx), pmul(dy, dy)), pmul(dz, dz));
            float2 d = upk2(dd);
            float m0 = fminf(mind[2 * r], d.x);
            mind[2 * r] = m0;
            if (m0 > bv) { bv = m0; bi = base + 2 * r; }
            float m1 = fminf(mind[2 * r + 1], d.y);
            mind[2 * r + 1] = m1;
            if (m1 > bv) { bv = m1; bi = base + 2 * r + 1; }
        }
        // argmax: values >= 0 so raw bits monotonic; low-index ties
        unsigned key  = __float_as_uint(bv);
        unsigned wmax = __reduce_max_sync(0xFFFFFFFFu, key);
        unsigned cand = (key == wmax) ? bi : 0xFFFFFFFFu;
        unsigned wi   = __reduce_min_sync(0xFFFFFFFFu, cand);
        if (lane == 0) { s_pk[w] = wmax; s_pi[w] = wi; }
        __syncthreads();
        if (w == 0) {
            unsigned kk = s_pk[lane], ii = s_pi[lane];
            unsigned gmax = __reduce_max_sync(0xFFFFFFFFu, kk);
            unsigned c2   = (kk == gmax) ? ii : 0xFFFFFFFFu;
            unsigned gi   = __reduce_min_sync(0xFFFFFFFFu, c2);
            if (lane == 0) {
                int pair = (int)(gi >> 1);
                float2 fx = upk2(sx[pair]);
                float2 fy = upk2(sy[pair]);
                float2 fz = upk2(sz[pair]);
                bool hi = (gi & 1u);
                s_last[0] = hi ? fx.y : fx.x;
                s_last[1] = hi ? fy.y : fy.x;
                s_last[2] = hi ? fz.y : fz.x;
                g_fps[b * NG + k] = (int)gi;
            }
        }
        __syncthreads();
    }

    // tail: centers + cnorms in FPS order
    if (t < NG) {
        int fi = g_fps[b * NG + t];
        float cx = X[fi], cy = Y[fi], cz = Z[fi];
        g_cent[(b * NG + t) * 3 + 0] = cx;
        g_cent[(b * NG + t) * 3 + 1] = cy;
        g_cent[(b * NG + t) * 3 + 2] = cz;
        g_cnorm[b * NG + t] = norm3(cx, cy, cz);
    }
}

// ---------------------------------------------------------------------------
// K2: blocks [0,16): morton chain. Blocks [16, 16+8192): KNN via radix-select.
// ---------------------------------------------------------------------------
__global__ void __launch_bounds__(256, 4) k_mk(const float* __restrict__ x) {
    __shared__ unsigned s_key[NP];        // 32KB keys (morton aliases this)
    __shared__ unsigned s_hist[2048];     // 8KB histogram
    __shared__ ull s_cand[32 + CAP2];     // 2KB candidates
    __shared__ unsigned s_wsum[8];
    __shared__ unsigned s_c1, s_c2, s_bstar, s_rb;
    __shared__ float s_xq[NC];
    __shared__ int s_knn[NM];
    __shared__ unsigned s_pk[8], s_pi[8], s_w;

    int t = threadIdx.x;
    int lane = t & 31, w = t >> 5;

    if (blockIdx.x < NB) {
        // ---------------- morton ----------------
        int b = blockIdx.x;
        float* s_cx = (float*)s_key;
        float* s_cy = s_cx + NG;
        float* s_cz = s_cx + 2 * NG;
        float* s_cn = s_cx + 3 * NG;
        for (int j = t; j < NG; j += 256) {
            s_cx[j] = g_cent[(b * NG + j) * 3 + 0];
            s_cy[j] = g_cent[(b * NG + j) * 3 + 1];
            s_cz[j] = g_cent[(b * NG + j) * 3 + 2];
            s_cn[j] = g_cnorm[b * NG + j];
        }
        if (t == 0) { s_w = 0; g_order[b * NG] = 0; }
        __syncthreads();

        int j1 = t, j2 = t + 256;
        float c1x = s_cx[j1], c1y = s_cy[j1], c1z = s_cz[j1], n1 = s_cn[j1];
        float c2x = s_cx[j2], c2y = s_cy[j2], c2z = s_cz[j2], n2 = s_cn[j2];
        bool a1 = (j1 != 0), a2 = true;

        for (int k = 1; k < NG; k++) {
            int wi0 = (int)s_w;
            float qx = s_cx[wi0], qy = s_cy[wi0], qz = s_cz[wi0], qn = s_cn[wi0];
            float dot1 = fmaf(qz, c1z, fmaf(qy, c1y, __fmul_rn(qx, c1x)));
            float d21 = __fsub_rn(__fadd_rn(qn, n1), __fmul_rn(2.0f, dot1));
            float dv1 = __fsqrt_rn(fmaxf(d21, 0.0f));
            unsigned k1 = a1 ? __float_as_uint(dv1) : 0xFFFFFFFFu;
            float dot2 = fmaf(qz, c2z, fmaf(qy, c2y, __fmul_rn(qx, c2x)));
            float d22 = __fsub_rn(__fadd_rn(qn, n2), __fmul_rn(2.0f, dot2));
            float dv2 = __fsqrt_rn(fmaxf(d22, 0.0f));
            unsigned k2 = a2 ? __float_as_uint(dv2) : 0xFFFFFFFFu;
            unsigned kk = (k1 <= k2) ? k1 : k2;
            unsigned ii = (k1 <= k2) ? (unsigned)j1 : (unsigned)j2;

            unsigned kmin = __reduce_min_sync(0xFFFFFFFFu, kk);
            unsigned cand = (kk == kmin) ? ii : 0xFFFFFFFFu;
            unsigned imin = __reduce_min_sync(0xFFFFFFFFu, cand);
            if (lane == 0) { s_pk[w] = kmin; s_pi[w] = imin; }
            __syncthreads();
            if (w == 0 && lane < 8) {
                unsigned kb = s_pk[lane], ib = s_pi[lane];
                unsigned gmin = __reduce_min_sync(0xFFu, kb);
                unsigned cb   = (kb == gmin) ? ib : 0xFFFFFFFFu;
                unsigned gi   = __reduce_min_sync(0xFFu, cb);
                if (lane == 0) { s_w = gi; g_order[b * NG + k] = (int)gi; }
            }
            __syncthreads();
            int wn = (int)s_w;
            if (j1 == wn) a1 = false;
            if (j2 == wn) a2 = false;
        }
        return;
    }

    // ---------------- knn (radix-select top-32) ----------------
    int bg = blockIdx.x - NB;
    int b = bg >> 9;
    float cx = g_cent[bg * 3 + 0];
    float cy = g_cent[bg * 3 + 1];
    float cz = g_cent[bg * 3 + 2];
    float nc = g_cnorm[bg];
    int qi = g_fps[bg];
    const float* xb = x + (size_t)b * NP * NC;
    if (t < NC) s_xq[t] = xb[(size_t)qi * NC + t];

    const float* X = &g_xt[(b * 3 + 0) * NP];
    const float* Y = &g_xt[(b * 3 + 1) * NP];
    const float* Z = &g_xt[(b * 3 + 2) * NP];

    // zero hist + counters
    for (int j = t; j < 2048; j += 256) s_hist[j] = 0;
    if (t == 0) { s_c1 = 0; s_c2 = 0; }
    __syncthreads();

    // distance + key + histogram (pn recomputed: bit-identical to norm3 tree)
#pragma unroll
    for (int r = 0; r < 32; r++) {
        int i = t + r * 256;
        float xx = X[i], yy = Y[i], zz = Z[i];
        float pn = norm3(xx, yy, zz);
        float dot = fmaf(cz, zz, fmaf(cy, yy, __fmul_rn(cx, xx))); // asc-fma
        float d2 = __fsub_rn(__fadd_rn(nc, pn), __fmul_rn(2.0f, dot));
        unsigned kk = fkey(d2);
        s_key[i] = kk;
        atomicAdd(&s_hist[kk >> 21], 1u);
    }
    __syncthreads();

    // block scan over 2048 bins -> find bin containing rank 32
    {
        int hb = t * 8;
        unsigned part = 0;
#pragma unroll
        for (int j = 0; j < 8; j++) part += s_hist[hb + j];
        unsigned inc = part;
#pragma unroll
        for (int d = 1; d < 32; d <<= 1) {
            unsigned v = __shfl_up_sync(0xFFFFFFFFu, inc, d);
            if (lane >= d) inc += v;
        }
        if (lane == 31) s_wsum[w] = inc;
        __syncthreads();
        if (w == 0 && lane < 8) {
            unsigned v = s_wsum[lane];
            unsigned inc2 = v;
#pragma unroll
            for (int d = 1; d < 8; d <<= 1) {
                unsigned u2 = __shfl_up_sync(0xFFu, inc2, d);
                if (lane >= d) inc2 += u2;
            }
            s_wsum[lane] = inc2 - v; // exclusive warp offset
        }
        __syncthreads();
        unsigned run = s_wsum[w] + inc - part; // exclusive prefix before bin hb
#pragma unroll
        for (int j = 0; j < 8; j++) {
            unsigned h = s_hist[hb + j];
            if (run < 32u && run + h >= 32u) { s_bstar = (unsigned)(hb + j); s_rb = run; }
            run += h;
        }
    }
    __syncthreads();

    unsigned bstar = s_bstar;
    // collect: bins < bstar -> definite; bin == bstar -> boundary candidates
#pragma unroll
    for (int r = 0; r < 32; r++) {
        int i = t + r * 256;
        unsigned kk = s_key[i];
        unsigned bin = kk >> 21;
        if (bin < bstar) {
            unsigned p = atomicAdd(&s_c1, 1u);
            s_cand[p] = ((ull)kk << 32) | (unsigned)i;
        } else if (bin == bstar) {
            unsigned p = atomicAdd(&s_c2, 1u);
            if (p < CAP2) s_cand[32 + p] = ((ull)kk << 32) | (unsigned)i;
        }
    }
    __syncthreads();

    if (s_c2 <= CAP2) {
        // rank-by-count over n1 + n2 candidates (unique ulls -> exact order)
        int n1 = (int)s_c1, n2 = (int)s_c2;
        for (int e = t; e < n1 + n2; e += 256) {
            int pos = (e < n1) ? e : 32 + (e - n1);
            ull v = s_cand[pos];
            unsigned rk = 0;
            for (int q = 0; q < n1; q++) rk += (s_cand[q] < v);
            for (int q = 0; q < n2; q++) rk += (s_cand[32 + q] < v);
            if (rk < 32u) s_knn[rk] = (int)(unsigned)(v & 0xFFFFFFFFull);
        }
        __syncthreads();
    } else {
        // fallback (degenerate tie storm): legacy 32-round selection on keys
        unsigned bk = 0xFFFFFFFFu, bi = 0xFFFFFFFFu;
#pragma unroll
        for (int r = 0; r < 32; r++) {
            int i = t + r * 256;
            unsigned kk = s_key[i];
            if (kk < bk) { bk = kk; bi = (unsigned)i; }
        }
        __syncthreads();
        for (int k = 0; k < NM; k++) {
            unsigned kmin = __reduce_min_sync(0xFFFFFFFFu, bk);
            unsigned cand = (bk == kmin) ? bi : 0xFFFFFFFFu;
            unsigned imin = __reduce_min_sync(0xFFFFFFFFu, cand);
            if (lane == 0) { s_pk[w] = kmin; s_pi[w] = imin; }
            __syncthreads();
            if (w == 0 && lane < 8) {
                unsigned kb = s_pk[lane], ib = s_pi[lane];
                unsigned gmin = __reduce_min_sync(0xFFu, kb);
                unsigned cb   = (kb == gmin) ? ib : 0xFFFFFFFFu;
                unsigned gi   = __reduce_min_sync(0xFFu, cb);
                if (lane == 0) { s_w = gi; s_knn[k] = (int)gi; }
            }
            __syncthreads();
            unsigned wi = s_w;
            if ((wi & 255u) == (unsigned)t) {
                s_key[wi] = 0xFFFFFFFFu;
                bk = 0xFFFFFFFFu; bi = 0xFFFFFFFFu;
#pragma unroll
                for (int r = 0; r < 32; r++) {
                    int i = t + r * 256;
                    unsigned kk = s_key[i];
                    if (kk < bk) { bk = kk; bi = (unsigned)i; }
                }
            }
        }
        __syncthreads();
    }

    // write nbh row (FPS order) to g_tmp
    float* trow = (float*)&g_tmp[(size_t)bg * 512];
    for (int v = t; v < NM * 2 * NC; v += 256) {
        int m = v >> 6, cc = v & 63;
        float val;
        if (cc < NC) val = __fsub_rn(xb[(size_t)s_knn[m] * NC + cc], s_xq[cc]);
        else         val = s_xq[cc - NC];
        trow[v] = val;
    }
}

// ---------------------------------------------------------------------------
// K3: scatter rows by morton order + write centers
// ---------------------------------------------------------------------------
__global__ void __launch_bounds__(256, 8) k_scat(float* __restrict__ out) {
    int bg = blockIdx.x;
    int b = bg >> 9;
    int t = threadIdx.x;
    int g = g_order[bg];
    const float4* src = &g_tmp[((size_t)b * NG + g) * 512];
    float4* dst = (float4*)out + (size_t)bg * 512;
    dst[t] = src[t];
    dst[t + 256] = src[t + 256];
    if (t < 3)
        out[(size_t)NB * NG * NM * 2 * NC + (size_t)bg * 3 + t] =
            g_cent[(b * NG + g) * 3 + t];
}

// ---------------------------------------------------------------------------
extern "C" void kernel_launch(void* const* d_in, const int* in_sizes, int n_in,
                              void* d_out, int out_size) {
    const float* x   = (const float*)d_in[0];
    const float* xyz = (const float*)d_in[1];
    if (n_in >= 2 && in_sizes[0] == NB * NP * 3) { // defensive: metadata order swap
        const float* tmp = x; x = xyz; xyz = tmp;
    }
    float* out = (float*)d_out;

    static bool inited = false;
    if (!inited) {
        cudaFuncSetAttribute(k_fps, cudaFuncAttributeMaxDynamicSharedMemorySize,
                             3 * 4096 * (int)sizeof(ull));
        inited = true;
    }

    k_pre<<<(NB * NP + 255) / 256, 256>>>(xyz);
    k_fps<<<NB, 1024, 3 * 4096 * sizeof(ull)>>>();
    k_mk<<<NB + NB * NG, 256>>>(x);
    k_scat<<<NB * NG, 256>>>(out);
}